// round 7
// baseline (speedup 1.0000x reference)
#include <cuda_runtime.h>
#include <cuda_bf16.h>
#include <mma.h>
#include <cstdint>

#define N_NODES 100000
#define N_PAD   100096            // 782 * 128, lets tail CTA store unguarded
#define N_EDGES 1600000
#define D 128
#define SCAN_BLK 1024
#define N_SCAN_BLOCKS ((N_NODES + SCAN_BLK - 1) / SCAN_BLK)   // 98

using namespace nvcuda;

// Device scratch (allocation-rule-compliant __device__ globals)
__device__ float          g_support[(size_t)N_PAD * D];   // 51.2+ MB
__device__ int            g_count[N_NODES];
__device__ int            g_cursor[N_NODES];
__device__ int            g_rowstart[N_NODES + 1];
__device__ int            g_blocksum[N_SCAN_BLOCKS];
__device__ int            g_csr_col[N_EDGES];
__device__ float          g_csr_val[N_EDGES];
// B split images, [k][n] row-major bf16 (wmma matrix_b row_major layout)
__device__ __nv_bfloat16  g_Bhi[128 * 128];
__device__ __nv_bfloat16  g_Blo[128 * 128];

// ---------------------------------------------------------------------------
// Prep: split W into hi/lo bf16, stored [k][n] (B operand for A[m,k]*B[k,n]).
// ---------------------------------------------------------------------------
__global__ void prep_b_kernel(const float* __restrict__ W) {
    int idx = blockIdx.x * blockDim.x + threadIdx.x;
    if (idx >= 128 * 128) return;
    float x = W[idx];                       // W is already [k][n]
    __nv_bfloat16 hi = __float2bfloat16(x);
    __nv_bfloat16 lo = __float2bfloat16(x - __bfloat162float(hi));
    g_Bhi[idx] = hi;
    g_Blo[idx] = lo;
}

// ---------------------------------------------------------------------------
// Tensor-core GEMM via wmma (HMMA, family-generic PTX safe):
//   g_support[M,128] = A[M,128] @ W[128,128]
//   fp32 -> (hi,lo) bf16 split; acc = Ahi*Bhi + Ahi*Blo + Alo*Bhi  (fp32 acc)
// CTA: 128x128 tile, 256 threads = 8 warps, warp tile 32x64 (2x4 fragments).
// ---------------------------------------------------------------------------
#define A_STRIDE 132                         // 264B rows (16B multiple), padded
#define B_STRIDE 128
#define AHI_OFF 0
#define ALO_OFF (128 * A_STRIDE)
#define BHI_OFF (2 * 128 * A_STRIDE)
#define BLO_OFF (2 * 128 * A_STRIDE + 128 * B_STRIDE)
#define SM_ELEMS (2 * 128 * A_STRIDE + 2 * 128 * B_STRIDE)
#define SM_BYTES (SM_ELEMS * 2)              // 133120

__global__ __launch_bounds__(256) void gemm_wmma_kernel(const float* __restrict__ A) {
    extern __shared__ __nv_bfloat16 sm[];
    const int tid = threadIdx.x;
    const int wid = tid >> 5;
    const int blockM = blockIdx.x * 128;

    // --- Copy B splits into SMEM (stride 128). 8 bf16 (16B) per iteration. ---
    {
#pragma unroll
        for (int it = 0; it < 8; it++) {
            int v = it * 256 + tid;          // 0..2047
            int row = v >> 4;                // 0..127
            int chunk = (v & 15) * 8;        // 0..120
            uint4 h = *reinterpret_cast<const uint4*>(g_Bhi + row * 128 + chunk);
            uint4 l = *reinterpret_cast<const uint4*>(g_Blo + row * 128 + chunk);
            *reinterpret_cast<uint4*>(sm + BHI_OFF + row * B_STRIDE + chunk) = h;
            *reinterpret_cast<uint4*>(sm + BLO_OFF + row * B_STRIDE + chunk) = l;
        }
    }

    // --- Convert A tile fp32 -> (hi,lo) bf16 into SMEM. 16 float4/thread. ---
#pragma unroll 4
    for (int it = 0; it < 16; it++) {
        int linear = it * 256 + tid;         // 0..4095
        int row = linear >> 5;               // 0..127
        int kq = (linear & 31) << 2;         // 0,4,...,124
        int gr = blockM + row;
        float4 v = make_float4(0.f, 0.f, 0.f, 0.f);
        if (gr < N_NODES)
            v = *reinterpret_cast<const float4*>(A + (size_t)gr * D + kq);

        __nv_bfloat16 h0 = __float2bfloat16(v.x), h1 = __float2bfloat16(v.y);
        __nv_bfloat16 h2 = __float2bfloat16(v.z), h3 = __float2bfloat16(v.w);
        __nv_bfloat16 l0 = __float2bfloat16(v.x - __bfloat162float(h0));
        __nv_bfloat16 l1 = __float2bfloat16(v.y - __bfloat162float(h1));
        __nv_bfloat16 l2 = __float2bfloat16(v.z - __bfloat162float(h2));
        __nv_bfloat16 l3 = __float2bfloat16(v.w - __bfloat162float(h3));

        __nv_bfloat16* ah = sm + AHI_OFF + row * A_STRIDE + kq;
        __nv_bfloat16* al = sm + ALO_OFF + row * A_STRIDE + kq;
        *reinterpret_cast<__nv_bfloat162*>(ah)     = __nv_bfloat162(h0, h1);
        *reinterpret_cast<__nv_bfloat162*>(ah + 2) = __nv_bfloat162(h2, h3);
        *reinterpret_cast<__nv_bfloat162*>(al)     = __nv_bfloat162(l0, l1);
        *reinterpret_cast<__nv_bfloat162*>(al + 2) = __nv_bfloat162(l2, l3);
    }
    __syncthreads();

    // --- Warp-tiled MMA: warp (wm, wn): wm = wid&3 (M), wn = wid>>2 (N) ---
    const int wm = (wid & 3) * 32;           // 0,32,64,96
    const int wn = (wid >> 2) * 64;          // 0,64

    wmma::fragment<wmma::accumulator, 16, 16, 16, float> acc[2][4];
#pragma unroll
    for (int i = 0; i < 2; i++)
#pragma unroll
        for (int j = 0; j < 4; j++) wmma::fill_fragment(acc[i][j], 0.0f);

    const int a_offs[3] = {AHI_OFF, AHI_OFF, ALO_OFF};
    const int b_offs[3] = {BHI_OFF, BLO_OFF, BHI_OFF};

#pragma unroll
    for (int sweep = 0; sweep < 3; sweep++) {
        const __nv_bfloat16* As = sm + a_offs[sweep];
        const __nv_bfloat16* Bs = sm + b_offs[sweep];
#pragma unroll
        for (int k0 = 0; k0 < 128; k0 += 16) {
            wmma::fragment<wmma::matrix_a, 16, 16, 16, __nv_bfloat16, wmma::row_major> af[2];
            wmma::fragment<wmma::matrix_b, 16, 16, 16, __nv_bfloat16, wmma::row_major> bf[4];
#pragma unroll
            for (int i = 0; i < 2; i++)
                wmma::load_matrix_sync(af[i], As + (wm + i * 16) * A_STRIDE + k0, A_STRIDE);
#pragma unroll
            for (int j = 0; j < 4; j++)
                wmma::load_matrix_sync(bf[j], Bs + k0 * B_STRIDE + wn + j * 16, B_STRIDE);
#pragma unroll
            for (int i = 0; i < 2; i++)
#pragma unroll
                for (int j = 0; j < 4; j++)
                    wmma::mma_sync(acc[i][j], af[i], bf[j], acc[i][j]);
        }
    }

    // --- Epilogue: direct store (g_support padded to N_PAD rows) ---
#pragma unroll
    for (int i = 0; i < 2; i++)
#pragma unroll
        for (int j = 0; j < 4; j++)
            wmma::store_matrix_sync(
                g_support + (size_t)(blockM + wm + i * 16) * D + wn + j * 16,
                acc[i][j], D, wmma::mem_row_major);
}

// ---------------------------------------------------------------------------
// CSR build
// ---------------------------------------------------------------------------
__global__ void zero_counts_kernel() {
    int i = blockIdx.x * blockDim.x + threadIdx.x;
    if (i < N_NODES) {
        g_count[i] = 0;
        g_cursor[i] = 0;
    }
}

__global__ void hist_kernel(const int* __restrict__ edge_row) {
    int e = blockIdx.x * blockDim.x + threadIdx.x;
    if (e < N_EDGES) atomicAdd(&g_count[edge_row[e]], 1);
}

__global__ __launch_bounds__(SCAN_BLK) void scan_local_kernel() {
    __shared__ int warp_sums[32];
    const int tid = threadIdx.x;
    const int lane = tid & 31;
    const int wid = tid >> 5;
    const int i = blockIdx.x * SCAN_BLK + tid;

    int x = (i < N_NODES) ? g_count[i] : 0;
    int v = x;
#pragma unroll
    for (int o = 1; o < 32; o <<= 1) {
        int t = __shfl_up_sync(0xFFFFFFFFu, v, o);
        if (lane >= o) v += t;
    }
    if (lane == 31) warp_sums[wid] = v;
    __syncthreads();
    if (tid < 32) {
        int w = warp_sums[tid];
#pragma unroll
        for (int o = 1; o < 32; o <<= 1) {
            int t = __shfl_up_sync(0xFFFFFFFFu, w, o);
            if (tid >= o) w += t;
        }
        warp_sums[tid] = w;
    }
    __syncthreads();
    int incl = v + (wid > 0 ? warp_sums[wid - 1] : 0);
    if (i < N_NODES) g_rowstart[i] = incl - x;
    if (tid == SCAN_BLK - 1) g_blocksum[blockIdx.x] = incl;
}

__global__ __launch_bounds__(128) void scan_blocks_kernel() {
    __shared__ int warp_sums[4];
    const int tid = threadIdx.x;
    const int lane = tid & 31;
    const int wid = tid >> 5;
    int x = (tid < N_SCAN_BLOCKS) ? g_blocksum[tid] : 0;
    int v = x;
#pragma unroll
    for (int o = 1; o < 32; o <<= 1) {
        int t = __shfl_up_sync(0xFFFFFFFFu, v, o);
        if (lane >= o) v += t;
    }
    if (lane == 31) warp_sums[wid] = v;
    __syncthreads();
    if (tid < 4) {
        int w = warp_sums[tid];
#pragma unroll
        for (int o = 1; o < 4; o <<= 1) {
            int t = __shfl_up_sync(0xFu, w, o);
            if (tid >= o) w += t;
        }
        warp_sums[tid] = w;
    }
    __syncthreads();
    int incl = v + (wid > 0 ? warp_sums[wid - 1] : 0);
    if (tid < N_SCAN_BLOCKS) g_blocksum[tid] = incl - x;
    if (tid == N_SCAN_BLOCKS - 1) g_rowstart[N_NODES] = incl;
}

__global__ __launch_bounds__(SCAN_BLK) void scan_addoff_kernel() {
    const int i = blockIdx.x * SCAN_BLK + threadIdx.x;
    if (i < N_NODES) g_rowstart[i] += g_blocksum[blockIdx.x];
}

__global__ void fill_kernel(const float* __restrict__ edge_val,
                            const int* __restrict__ edge_row,
                            const int* __restrict__ edge_col) {
    int e = blockIdx.x * blockDim.x + threadIdx.x;
    if (e < N_EDGES) {
        int r = edge_row[e];
        int p = g_rowstart[r] + atomicAdd(&g_cursor[r], 1);
        g_csr_col[p] = edge_col[e];
        g_csr_val[p] = edge_val[e];
    }
}

// ---------------------------------------------------------------------------
// Gather: one warp per output row. acc = sum(val * support[col]); ReLU; store.
// ---------------------------------------------------------------------------
__global__ __launch_bounds__(256) void gather_kernel(float* __restrict__ out) {
    int row = blockIdx.x * 8 + (threadIdx.x >> 5);
    int lane = threadIdx.x & 31;
    if (row >= N_NODES) return;

    int s = g_rowstart[row];
    int e = g_rowstart[row + 1];

    float4 acc = make_float4(0.f, 0.f, 0.f, 0.f);
#pragma unroll 4
    for (int i = s; i < e; i++) {
        int c = g_csr_col[i];
        float v = g_csr_val[i];
        float4 sv = *reinterpret_cast<const float4*>(g_support + (size_t)c * D + lane * 4);
        acc.x = fmaf(v, sv.x, acc.x);
        acc.y = fmaf(v, sv.y, acc.y);
        acc.z = fmaf(v, sv.z, acc.z);
        acc.w = fmaf(v, sv.w, acc.w);
    }

    acc.x = fmaxf(acc.x, 0.f);
    acc.y = fmaxf(acc.y, 0.f);
    acc.z = fmaxf(acc.z, 0.f);
    acc.w = fmaxf(acc.w, 0.f);
    *reinterpret_cast<float4*>(out + (size_t)row * D + lane * 4) = acc;
}

extern "C" void kernel_launch(void* const* d_in, const int* in_sizes, int n_in,
                              void* d_out, int out_size) {
    const float* features = (const float*)d_in[0];   // [100000, 128]
    const float* weight   = (const float*)d_in[1];   // [128, 128]
    const float* edge_val = (const float*)d_in[2];   // [1600000]
    const int*   edge_row = (const int*)d_in[3];     // [1600000]
    const int*   edge_col = (const int*)d_in[4];     // [1600000]
    float* out = (float*)d_out;                      // [100000, 128]

    // Unconditional (no static guards allowed). Not a stream op; capture-safe.
    cudaFuncSetAttribute(gemm_wmma_kernel,
                         cudaFuncAttributeMaxDynamicSharedMemorySize, SM_BYTES);

    // 1) support = features @ W  (wmma split-bf16)
    prep_b_kernel<<<64, 256>>>(weight);
    gemm_wmma_kernel<<<N_PAD / 128, 256, SM_BYTES>>>(features);

    // 2) CSR build with hierarchical scan
    zero_counts_kernel<<<(N_NODES + 255) / 256, 256>>>();
    hist_kernel<<<(N_EDGES + 255) / 256, 256>>>(edge_row);
    scan_local_kernel<<<N_SCAN_BLOCKS, SCAN_BLK>>>();
    scan_blocks_kernel<<<1, 128>>>();
    scan_addoff_kernel<<<N_SCAN_BLOCKS, SCAN_BLK>>>();
    fill_kernel<<<(N_EDGES + 255) / 256, 256>>>(edge_val, edge_row, edge_col);

    // 3) fused gather + ReLU -> out
    gather_kernel<<<(N_NODES + 7) / 8, 256>>>(out);
}